// round 1
// baseline (speedup 1.0000x reference)
#include <cuda_runtime.h>
#include <math.h>

#define NMAX 100000
#define EMAX 1600000
#define SCAN_T 512

// ---------------- scratch (device globals; no allocation at runtime) --------
__device__ float g_deg[NMAX];
__device__ float g_dinv[NMAX];
__device__ int   g_cnt[NMAX];
__device__ int   g_fill[NMAX];
__device__ int   g_rowptr[NMAX + 1];
__device__ int   g_bsum[SCAN_T];
__device__ int   g_es[EMAX];     // src sorted by dst
__device__ float g_en[EMAX];     // norm sorted by dst
__device__ float g_A[(size_t)NMAX * 72];    // [AX | AH]
__device__ float g_Wc[72 * 256];            // combined gate weights
__device__ float g_bc[256];                 // combined gate bias (bx+bh+bg)
__device__ float g_G[(size_t)NMAX * 256];   // gate preactivations
__device__ float g_y[(size_t)NMAX * 64];    // cat(relu(LN_o(h)),skip) @ W1
__device__ float g_t[NMAX];                 // scalar per node before final agg

// ---------------- small helpers ---------------------------------------------
__device__ __forceinline__ float sigmoidf_(float x) { return 1.f / (1.f + __expf(-x)); }
__device__ __forceinline__ float warp_sum(float v) {
#pragma unroll
    for (int o = 16; o > 0; o >>= 1) v += __shfl_xor_sync(0xffffffffu, v, o);
    return v;
}

// ---------------- graph norm + CSR build -------------------------------------
__global__ void k_init(int n) {
    int i = blockIdx.x * blockDim.x + threadIdx.x;
    if (i < n) { g_deg[i] = 1.0f; g_cnt[i] = 0; g_fill[i] = 0; }
}

__global__ void k_count(const int* __restrict__ dst, const float* __restrict__ w, int E) {
    int e = blockIdx.x * blockDim.x + threadIdx.x;
    if (e < E) {
        int d = dst[e];
        atomicAdd(&g_deg[d], w[e]);
        atomicAdd(&g_cnt[d], 1);
    }
}

__global__ void k_dinv(int n) {
    int i = blockIdx.x * blockDim.x + threadIdx.x;
    if (i < n) g_dinv[i] = rsqrtf(fmaxf(g_deg[i], 1e-12f));
}

__global__ void k_scan1(int n) {
    __shared__ int sh[SCAN_T];
    int t = threadIdx.x;
    int i = blockIdx.x * SCAN_T + t;
    int v = (i < n) ? g_cnt[i] : 0;
    sh[t] = v;
#pragma unroll
    for (int off = 1; off < SCAN_T; off <<= 1) {
        __syncthreads();
        int x = (t >= off) ? sh[t - off] : 0;
        __syncthreads();
        sh[t] += x;
    }
    __syncthreads();
    if (i < n) g_rowptr[i] = sh[t] - v;          // exclusive within block
    if (t == SCAN_T - 1) g_bsum[blockIdx.x] = sh[t];
}

__global__ void k_scan2(int nblk) {
    __shared__ int sh[SCAN_T];
    int t = threadIdx.x;
    int v = (t < nblk) ? g_bsum[t] : 0;
    sh[t] = v;
#pragma unroll
    for (int off = 1; off < SCAN_T; off <<= 1) {
        __syncthreads();
        int x = (t >= off) ? sh[t - off] : 0;
        __syncthreads();
        sh[t] += x;
    }
    __syncthreads();
    if (t < nblk) g_bsum[t] = sh[t] - v;          // exclusive block offsets
}

__global__ void k_scan3(int n, int E) {
    int i = blockIdx.x * blockDim.x + threadIdx.x;
    if (i < n) g_rowptr[i] += g_bsum[i / SCAN_T];
    if (i == 0) g_rowptr[n] = E;
}

__global__ void k_scatter(const int* __restrict__ src, const int* __restrict__ dst,
                          const float* __restrict__ w, int E) {
    int e = blockIdx.x * blockDim.x + threadIdx.x;
    if (e < E) {
        int d = dst[e];
        int s = src[e];
        int pos = g_rowptr[d] + atomicAdd(&g_fill[d], 1);
        g_es[pos] = s;
        g_en[pos] = g_dinv[d] * w[e] * g_dinv[s];
    }
}

// ---------------- weight prep ------------------------------------------------
__global__ void k_prepw(const float* __restrict__ Wx, const float* __restrict__ Wh,
                        const float* __restrict__ bx, const float* __restrict__ bh,
                        const float* __restrict__ bg) {
    int k = blockIdx.x;          // 0..71
    int c = threadIdx.x;         // 0..255 -> gate g = c>>6, col j = c&63
    int g = c >> 6, j = c & 63;
    g_Wc[k * 256 + c] = (k < 8) ? Wx[g * 512 + k * 64 + j]
                                : Wh[g * 4096 + (k - 8) * 64 + j];
    if (k == 0) g_bc[c] = bx[c] + bh[c] + bg[c];
}

// ---------------- aggregation 1: A = [agg(X) | agg(H)] ----------------------
__global__ void k_agg1(const float* __restrict__ X, const float* __restrict__ H, int n) {
    int warp = threadIdx.x >> 5, lane = threadIdx.x & 31;
    int node = blockIdx.x * (blockDim.x >> 5) + warp;
    if (node >= n) return;
    float di = g_dinv[node];
    float coef = di * di;                       // self loop (w=1)
    float ax  = (lane < 8) ? coef * X[node * 8 + lane] : 0.f;
    float ah0 = coef * H[node * 64 + lane];
    float ah1 = coef * H[node * 64 + 32 + lane];
    int e0 = g_rowptr[node], e1 = g_rowptr[node + 1];
    for (int e = e0; e < e1; e++) {
        int s = g_es[e];
        float nm = g_en[e];
        ah0 += nm * H[s * 64 + lane];
        ah1 += nm * H[s * 64 + 32 + lane];
        if (lane < 8) ax += nm * X[s * 8 + lane];
    }
    float* Arow = g_A + (size_t)node * 72;
    if (lane < 8) Arow[lane] = ax;
    Arow[8 + lane]  = ah0;
    Arow[40 + lane] = ah1;
}

// ---------------- gate GEMM: G[N,256] = A[N,72] @ Wc + bias ------------------
__global__ void __launch_bounds__(256, 2) k_gemm(int n) {
    extern __shared__ float smem[];
    float* As = smem;              // 64 * 72
    float* Ws = smem + 64 * 72;    // 72 * 256
    int nb = blockIdx.x * 64;
    for (int idx = threadIdx.x; idx < 64 * 72; idx += 256) {
        int r = idx / 72, c = idx % 72;
        int node = nb + r;
        As[idx] = (node < n) ? g_A[(size_t)node * 72 + c] : 0.f;
    }
    for (int idx = threadIdx.x; idx < 72 * 256; idx += 256) Ws[idx] = g_Wc[idx];
    __syncthreads();

    int tg = threadIdx.x >> 5;     // node group 0..7 (8 nodes each)
    int cg = threadIdx.x & 31;     // col group 0..31 (8 cols each)
    float acc[8][8];
#pragma unroll
    for (int i = 0; i < 8; i++)
#pragma unroll
        for (int j = 0; j < 8; j++) acc[i][j] = 0.f;

#pragma unroll 2
    for (int k = 0; k < 72; k++) {
        float4 w0 = *reinterpret_cast<const float4*>(Ws + k * 256 + cg * 8);
        float4 w1 = *reinterpret_cast<const float4*>(Ws + k * 256 + cg * 8 + 4);
        float wv0 = w0.x, wv1 = w0.y, wv2 = w0.z, wv3 = w0.w;
        float wv4 = w1.x, wv5 = w1.y, wv6 = w1.z, wv7 = w1.w;
#pragma unroll
        for (int i = 0; i < 8; i++) {
            float a = As[(tg * 8 + i) * 72 + k];
            acc[i][0] += a * wv0; acc[i][1] += a * wv1;
            acc[i][2] += a * wv2; acc[i][3] += a * wv3;
            acc[i][4] += a * wv4; acc[i][5] += a * wv5;
            acc[i][6] += a * wv6; acc[i][7] += a * wv7;
        }
    }

    float4 b0 = *reinterpret_cast<const float4*>(g_bc + cg * 8);
    float4 b1 = *reinterpret_cast<const float4*>(g_bc + cg * 8 + 4);
#pragma unroll
    for (int i = 0; i < 8; i++) {
        int node = nb + tg * 8 + i;
        if (node < n) {
            float4 o0 = make_float4(acc[i][0] + b0.x, acc[i][1] + b0.y,
                                    acc[i][2] + b0.z, acc[i][3] + b0.w);
            float4 o1 = make_float4(acc[i][4] + b1.x, acc[i][5] + b1.y,
                                    acc[i][6] + b1.z, acc[i][7] + b1.w);
            *reinterpret_cast<float4*>(g_G + (size_t)node * 256 + cg * 8)     = o0;
            *reinterpret_cast<float4*>(g_G + (size_t)node * 256 + cg * 8 + 4) = o1;
        }
    }
}

// ---------------- LSTM elementwise + 3 LN + head GEMM (y = cat @ W1) ---------
__global__ void k_lstm(const float* __restrict__ C, const float* __restrict__ wc,
                       const float* __restrict__ lnhs, const float* __restrict__ lnhb,
                       const float* __restrict__ lncs, const float* __restrict__ lncb,
                       const float* __restrict__ lnos, const float* __restrict__ lnob,
                       const float* __restrict__ skip, const float* __restrict__ W1,
                       float* __restrict__ outHidden, float* __restrict__ outCell, int n) {
    __shared__ float W1s[66 * 64];
    for (int i = threadIdx.x; i < 66 * 64; i += blockDim.x) W1s[i] = W1[i];
    __syncthreads();

    int warp = threadIdx.x >> 5, lane = threadIdx.x & 31;
    int node = blockIdx.x * (blockDim.x >> 5) + warp;
    if (node >= n) return;

    const float* Grow = g_G + (size_t)node * 256;
    int j0 = lane, j1 = lane + 32;
    float g0a = Grow[j0],        g0b = Grow[j1];
    float g1a = Grow[64 + j0],   g1b = Grow[64 + j1];
    float g2a = Grow[128 + j0],  g2b = Grow[128 + j1];
    float g3a = Grow[192 + j0],  g3b = Grow[192 + j1];
    float c0a = C[node * 64 + j0], c0b = C[node * 64 + j1];

    float ia = sigmoidf_(g0a + wc[j0] * c0a),       ib = sigmoidf_(g0b + wc[j1] * c0b);
    float fa = sigmoidf_(g1a + wc[64 + j0] * c0a),  fb = sigmoidf_(g1b + wc[64 + j1] * c0b);
    float ca = fa * c0a + ia * tanhf(g2a);
    float cb = fb * c0b + ib * tanhf(g2b);
    float oa = sigmoidf_(g3a + wc[128 + j0] * ca),  ob = sigmoidf_(g3b + wc[128 + j1] * cb);
    float ha = oa * tanhf(ca),                      hb = ob * tanhf(cb);

    // LN over h (shared by hidden-LN and out-LN)
    float mh = warp_sum(ha + hb) * (1.f / 64.f);
    float dha = ha - mh, dhb = hb - mh;
    float vh = warp_sum(dha * dha + dhb * dhb) * (1.f / 64.f);
    float rh = rsqrtf(vh + 1e-5f);
    outHidden[node * 64 + j0] = dha * rh * lnhs[j0] + lnhb[j0];
    outHidden[node * 64 + j1] = dhb * rh * lnhs[j1] + lnhb[j1];

    // LN over c
    float mc = warp_sum(ca + cb) * (1.f / 64.f);
    float dca = ca - mc, dcb = cb - mc;
    float vc = warp_sum(dca * dca + dcb * dcb) * (1.f / 64.f);
    float rc = rsqrtf(vc + 1e-5f);
    outCell[node * 64 + j0] = dca * rc * lncs[j0] + lncb[j0];
    outCell[node * 64 + j1] = dcb * rc * lncs[j1] + lncb[j1];

    // relu(LN_o(h)), then y = cat(r, skip) @ W1  (b1 added after agg2)
    float r0 = fmaxf(dha * rh * lnos[j0] + lnob[j0], 0.f);
    float r1 = fmaxf(dhb * rh * lnos[j1] + lnob[j1], 0.f);
    float s0 = skip[node * 2], s1 = skip[node * 2 + 1];
    float y0 = s0 * W1s[64 * 64 + j0] + s1 * W1s[65 * 64 + j0];
    float y1 = s0 * W1s[64 * 64 + j1] + s1 * W1s[65 * 64 + j1];
#pragma unroll
    for (int k = 0; k < 32; k++) {
        float rk = __shfl_sync(0xffffffffu, r0, k);
        y0 += rk * W1s[k * 64 + j0];
        y1 += rk * W1s[k * 64 + j1];
    }
#pragma unroll
    for (int k = 0; k < 32; k++) {
        float rk = __shfl_sync(0xffffffffu, r1, k);
        y0 += rk * W1s[(32 + k) * 64 + j0];
        y1 += rk * W1s[(32 + k) * 64 + j1];
    }
    g_y[(size_t)node * 64 + j0] = y0;
    g_y[(size_t)node * 64 + j1] = y1;
}

// ---------------- agg2 on y, then t = relu(z+b1) . W2 -----------------------
__global__ void k_agg2(const float* __restrict__ b1, const float* __restrict__ W2, int n) {
    int warp = threadIdx.x >> 5, lane = threadIdx.x & 31;
    int node = blockIdx.x * (blockDim.x >> 5) + warp;
    if (node >= n) return;
    float di = g_dinv[node];
    float coef = di * di;
    int j0 = lane, j1 = lane + 32;
    float z0 = coef * g_y[(size_t)node * 64 + j0];
    float z1 = coef * g_y[(size_t)node * 64 + j1];
    int e0 = g_rowptr[node], e1 = g_rowptr[node + 1];
    for (int e = e0; e < e1; e++) {
        int s = g_es[e];
        float nm = g_en[e];
        z0 += nm * g_y[(size_t)s * 64 + j0];
        z1 += nm * g_y[(size_t)s * 64 + j1];
    }
    float u0 = fmaxf(z0 + b1[j0], 0.f);
    float u1 = fmaxf(z1 + b1[j1], 0.f);
    float p = warp_sum(u0 * W2[j0] + u1 * W2[j1]);
    if (lane == 0) g_t[node] = p;
}

// ---------------- agg3 (1-wide) + b2 + residual -> out -----------------------
__global__ void k_agg3(const float* __restrict__ X, const float* __restrict__ b2,
                       float* __restrict__ out, int n) {
    int node = blockIdx.x * blockDim.x + threadIdx.x;
    if (node >= n) return;
    float di = g_dinv[node];
    float s = di * di * g_t[node];
    int e0 = g_rowptr[node], e1 = g_rowptr[node + 1];
    for (int e = e0; e < e1; e++) s += g_en[e] * g_t[g_es[e]];
    out[node] = s + b2[0] + X[node * 8];
}

// ---------------- launch -----------------------------------------------------
extern "C" void kernel_launch(void* const* d_in, const int* in_sizes, int n_in,
                              void* d_out, int out_size) {
    const float* X    = (const float*)d_in[0];
    const int*   ei   = (const int*)d_in[1];
    const float* ew   = (const float*)d_in[2];
    const float* skip = (const float*)d_in[3];
    const float* H    = (const float*)d_in[4];
    const float* C    = (const float*)d_in[5];
    const float* Wx   = (const float*)d_in[6];
    const float* bx   = (const float*)d_in[7];
    const float* Wh   = (const float*)d_in[8];
    const float* bh   = (const float*)d_in[9];
    const float* wc   = (const float*)d_in[10];
    const float* bg   = (const float*)d_in[11];
    const float* lnhs = (const float*)d_in[12];
    const float* lnhb = (const float*)d_in[13];
    const float* lncs = (const float*)d_in[14];
    const float* lncb = (const float*)d_in[15];
    const float* lnos = (const float*)d_in[16];
    const float* lnob = (const float*)d_in[17];
    const float* W1   = (const float*)d_in[18];
    const float* b1   = (const float*)d_in[19];
    const float* W2   = (const float*)d_in[20];
    const float* b2   = (const float*)d_in[21];

    int n = in_sizes[0] / 8;
    int E = in_sizes[1] / 2;
    if (n > NMAX) n = NMAX;
    if (E > EMAX) E = EMAX;
    const int* src = ei;
    const int* dst = ei + E;

    float* out       = (float*)d_out;
    float* outHidden = out + n;
    float* outCell   = outHidden + (size_t)n * 64;

    int nblkN  = (n + 255) / 256;
    int nblkE  = (E + 255) / 256;
    int nblkS  = (n + SCAN_T - 1) / SCAN_T;
    int nblkW  = (n + 7) / 8;          // warp-per-node kernels, 256 threads

    // graph norm + CSR
    k_init<<<nblkN, 256>>>(n);
    k_count<<<nblkE, 256>>>(dst, ew, E);
    k_dinv<<<nblkN, 256>>>(n);
    k_scan1<<<nblkS, SCAN_T>>>(n);
    k_scan2<<<1, SCAN_T>>>(nblkS);
    k_scan3<<<nblkN, 256>>>(n, E);
    k_scatter<<<nblkE, 256>>>(src, dst, ew, E);

    // weights
    k_prepw<<<72, 256>>>(Wx, Wh, bx, bh, bg);

    // agg1 -> A
    k_agg1<<<nblkW, 256>>>(X, H, n);

    // gate GEMM
    const int GEMM_SMEM = (64 * 72 + 72 * 256) * (int)sizeof(float);
    cudaFuncSetAttribute(k_gemm, cudaFuncAttributeMaxDynamicSharedMemorySize, GEMM_SMEM);
    k_gemm<<<(n + 63) / 64, 256, GEMM_SMEM>>>(n);

    // LSTM + LN + head pre-GEMM
    k_lstm<<<nblkW, 256>>>(C, wc, lnhs, lnhb, lncs, lncb, lnos, lnob,
                           skip, W1, outHidden, outCell, n);

    // agg2 + fc epilogue -> t ; agg3 -> out
    k_agg2<<<nblkW, 256>>>(b1, W2, n);
    k_agg3<<<nblkN, 256>>>(X, b2, out, n);
}